// round 2
// baseline (speedup 1.0000x reference)
#include <cuda_runtime.h>
#include <cstdint>

// out[t, v] = bias[v] + sum_{q=0..3} W[v][q] * cos(x[t])^(q+1)
// (closed form of the CNOT-permuted Ry product state; phase cancels in |psi|^2)
//
// Store-bandwidth-bound: 168MB out + 4MB in. Strategy: minimize issue count per
// STG.128 so the LSU/LTS path saturates.
//   phase 1: thread tid computes u=__cosf(x), writes DUPLICATED packs
//            {u,u},{u2,u2} and {u3,u3},{u4,u4} to smem (ready for f32x2 FMA).
//   phase 2: 10 iters; thread owns v-group vv=tid%10, coefficients packed as
//            f32x2 in registers; 2 LDS.128 (broadcast) + 8 fma.rn.f32x2 + 1 STG.128.
//            Store address == out_bytes + base*160 + tid*16 + it*5120 (contiguous/warp).

#define NT 320

#define PACK2(o, lo, hi) \
    asm("mov.b64 %0, {%1, %2};" : "=l"(o) : "f"(lo), "f"(hi))
#define FMA2(d, a, b, c) \
    asm("fma.rn.f32x2 %0, %1, %2, %3;" : "=l"(d) : "l"(a), "l"(b), "l"(c))

__global__ void __launch_bounds__(NT, 5)
qmodel_kernel(const float* __restrict__ x,
              const float* __restrict__ W,     // (40,4) row-major
              const float* __restrict__ bias,  // (40,)
              float* __restrict__ out,         // (SEQ,40)
              int seq)
{
    __shared__ ulonglong2 suA[NT];   // {u,u},{u2,u2}
    __shared__ ulonglong2 suB[NT];   // {u3,u3},{u4,u4}

    const int tid = threadIdx.x;
    const long long base = (long long)blockIdx.x * NT;

    // ---- packed per-thread coefficients for v-group vv (outputs v0..v0+3) ----
    const int vv = tid % 10;
    const int v0 = vv * 4;
    const float4 w0 = ((const float4*)W)[v0 + 0];
    const float4 w1 = ((const float4*)W)[v0 + 1];
    const float4 w2 = ((const float4*)W)[v0 + 2];
    const float4 w3 = ((const float4*)W)[v0 + 3];

    unsigned long long c0a, c0b, c1a, c1b, c2a, c2b, c3a, c3b, c4a, c4b;
    PACK2(c0a, bias[v0],   bias[v0+1]);
    PACK2(c0b, bias[v0+2], bias[v0+3]);
    PACK2(c1a, w0.x, w1.x);  PACK2(c1b, w2.x, w3.x);
    PACK2(c2a, w0.y, w1.y);  PACK2(c2b, w2.y, w3.y);
    PACK2(c3a, w0.z, w1.z);  PACK2(c3b, w2.z, w3.z);
    PACK2(c4a, w0.w, w1.w);  PACK2(c4b, w2.w, w3.w);

    // ---- phase 1: duplicated powers of cos(x) into smem ----
    {
        long long t = base + tid;
        if (t < seq) {
            float u  = __cosf(x[t]);
            float u2 = u * u;
            float u3 = u2 * u;
            float u4 = u2 * u2;
            unsigned long long pu, pu2, pu3, pu4;
            PACK2(pu,  u,  u);
            PACK2(pu2, u2, u2);
            PACK2(pu3, u3, u3);
            PACK2(pu4, u4, u4);
            suA[tid] = make_ulonglong2(pu,  pu2);
            suB[tid] = make_ulonglong2(pu3, pu4);
        }
    }
    __syncthreads();

    // ---- phase 2: evaluate + store ----
    const int tt0 = tid / 10;                         // 0..31
    // float4-granular output pointer: index = base*10 + tid + it*320
    ulonglong2* __restrict__ op = ((ulonglong2*)out) + base * 10 + tid;

    const bool full = (base + NT <= (long long)seq);

    if (full) {
        #pragma unroll
        for (int it = 0; it < 10; ++it) {
            ulonglong2 a = suA[it * 32 + tt0];
            ulonglong2 b = suB[it * 32 + tt0];
            unsigned long long r01, r23;
            FMA2(r01, c1a, a.x, c0a);
            FMA2(r23, c1b, a.x, c0b);
            FMA2(r01, c2a, a.y, r01);
            FMA2(r23, c2b, a.y, r23);
            FMA2(r01, c3a, b.x, r01);
            FMA2(r23, c3b, b.x, r23);
            FMA2(r01, c4a, b.y, r01);
            FMA2(r23, c4b, b.y, r23);
            op[it * (NT / 10) * 10] = make_ulonglong2(r01, r23);  // +320 float4 / iter
        }
    } else {
        #pragma unroll
        for (int it = 0; it < 10; ++it) {
            long long t = base + it * 32 + tt0;
            if (t < seq) {
                ulonglong2 a = suA[it * 32 + tt0];
                ulonglong2 b = suB[it * 32 + tt0];
                unsigned long long r01, r23;
                FMA2(r01, c1a, a.x, c0a);
                FMA2(r23, c1b, a.x, c0b);
                FMA2(r01, c2a, a.y, r01);
                FMA2(r23, c2b, a.y, r23);
                FMA2(r01, c3a, b.x, r01);
                FMA2(r23, c3b, b.x, r23);
                FMA2(r01, c4a, b.y, r01);
                FMA2(r23, c4b, b.y, r23);
                op[it * 320] = make_ulonglong2(r01, r23);
            }
        }
    }
}

extern "C" void kernel_launch(void* const* d_in, const int* in_sizes, int n_in,
                              void* d_out, int out_size)
{
    const float* x    = (const float*)d_in[0];
    // d_in[1] = q_weights: unused (global phase cancels in |psi|^2)
    const float* W    = (const float*)d_in[2];
    const float* bias = (const float*)d_in[3];
    float* out        = (float*)d_out;

    const int seq = in_sizes[0];
    const int blocks = (seq + NT - 1) / NT;
    qmodel_kernel<<<blocks, NT>>>(x, W, bias, out, seq);
}